// round 4
// baseline (speedup 1.0000x reference)
#include <cuda_runtime.h>
#include <cuda_bf16.h>
#include <cstdint>

#define NG 128
#define NPMAX 200000
#define NRMAX 400000

// ---- static scratch ----
__device__ __align__(16) float g_p_y  [NPMAX * 64];
__device__ __align__(16) float g_r_y  [NRMAX * 64];
__device__ __align__(16) float g_p_acc[NPMAX * 64];
__device__ __align__(16) float g_r_acc[NRMAX * 64];
__device__ float g_p_dinv[NPMAX];
__device__ float g_r_dinv[NRMAX];
__device__ float g_pool[NG * 128];
__device__ float g_cnt[2 * NG];
__device__ __align__(16) __nv_bfloat16 g_pWhi[64 * 1280];
__device__ __align__(16) __nv_bfloat16 g_pWlo[64 * 1280];
__device__ __align__(16) __nv_bfloat16 g_rWhi[64 * 128];
__device__ __align__(16) __nv_bfloat16 g_rWlo[64 * 128];

__device__ __forceinline__ uint32_t smem_u32(const void* p) {
    uint32_t a;
    asm("{ .reg .u64 t; cvta.to.shared.u64 t, %1; cvt.u32.u64 %0, t; }" : "=r"(a) : "l"(p));
    return a;
}

__device__ __forceinline__ void ldm_x4(uint32_t* r, uint32_t addr) {
    asm volatile("ldmatrix.sync.aligned.m8n8.x4.shared.b16 {%0,%1,%2,%3}, [%4];"
                 : "=r"(r[0]), "=r"(r[1]), "=r"(r[2]), "=r"(r[3]) : "r"(addr));
}

__device__ __forceinline__ void mma_bf16(float* d, const uint32_t* a, const uint32_t* b) {
    asm volatile(
        "mma.sync.aligned.m16n8k16.row.col.f32.bf16.bf16.f32 "
        "{%0,%1,%2,%3}, {%4,%5,%6,%7}, {%8,%9}, {%0,%1,%2,%3};"
        : "+f"(d[0]), "+f"(d[1]), "+f"(d[2]), "+f"(d[3])
        : "r"(a[0]), "r"(a[1]), "r"(a[2]), "r"(a[3]), "r"(b[0]), "r"(b[1]));
}

// ---------------------------------------------------------------------------
// init (deg=1, pool/cnt=0) + W hi/lo split, all fused
// ---------------------------------------------------------------------------
__global__ void k_init(int np, int nr,
                       const float* __restrict__ pW, const float* __restrict__ rW,
                       int Kp, int KpPad, int Kr, int KrPad) {
    int i = blockIdx.x * blockDim.x + threadIdx.x;
    if (i < np) g_p_dinv[i] = 1.0f;
    if (i < nr) g_r_dinv[i] = 1.0f;
    if (i < NG * 128) g_pool[i] = 0.0f;
    if (i < 2 * NG) g_cnt[i] = 0.0f;
    if (i < 64 * KpPad) {
        int n = i / KpPad, k = i % KpPad;
        float v = (k < Kp) ? pW[k * 64 + n] : 0.0f;
        __nv_bfloat16 h = __float2bfloat16_rn(v);
        g_pWhi[i] = h;
        g_pWlo[i] = __float2bfloat16_rn(v - __bfloat162float(h));
    }
    if (i < 64 * KrPad) {
        int n = i / KrPad, k = i % KrPad;
        float v = (k < Kr) ? rW[k * 64 + n] : 0.0f;
        __nv_bfloat16 h = __float2bfloat16_rn(v);
        g_rWhi[i] = h;
        g_rWlo[i] = __float2bfloat16_rn(v - __bfloat162float(h));
    }
}

__global__ void k_count(const int* __restrict__ dst, int E, float* __restrict__ deg) {
    int e = blockIdx.x * blockDim.x + threadIdx.x;
    if (e < E) atomicAdd(&deg[dst[e]], 1.0f);
}

__global__ void k_dinv(float* __restrict__ d, int n) {
    int i = blockIdx.x * blockDim.x + threadIdx.x;
    if (i < n) d[i] = rsqrtf(d[i]);
}

// ---------------------------------------------------------------------------
// HMMA GEMM, bf16x3, register-prefetch double buffering.
// CTA: 128 rows x 64 cols, 256 threads. Epilogue writes y = xw*dinv to both
// Y and ACC (self-loop term of acc).
// ---------------------------------------------------------------------------
#define KC 64
#define APAD 8
#define ASTR (KC + APAD)
#define SZ_A (128 * ASTR)
#define SZ_B (64 * ASTR)
extern __shared__ __align__(16) __nv_bfloat16 dynsm[];

__global__ __launch_bounds__(256) void k_gemm_mma(
    const float* __restrict__ X,
    const __nv_bfloat16* __restrict__ Whi, const __nv_bfloat16* __restrict__ Wlo,
    const float* __restrict__ dinv,
    float* __restrict__ Y, float* __restrict__ ACC,
    int M, int K, int Kpad)
{
    __nv_bfloat16* sAhi = dynsm;
    __nv_bfloat16* sAlo = dynsm + SZ_A;
    __nv_bfloat16* sBhi = dynsm + 2 * SZ_A;
    __nv_bfloat16* sBlo = dynsm + 2 * SZ_A + SZ_B;
    uint32_t uAhi = smem_u32(sAhi), uAlo = smem_u32(sAlo);

    int tid = threadIdx.x;
    int w = tid >> 5, lane = tid & 31;
    int g = lane >> 2, tg = lane & 3;

    int arow = tid >> 1;
    int akh  = (tid & 1) * 32;
    int grow = blockIdx.x * 128 + arow;
    bool aOK = grow < M;
    const float* xrow = X + (size_t)grow * K;

    int bt = tid & 127;
    int bn = bt >> 1;
    int bkh = (bt & 1) * 32;
    const __nv_bfloat16* bsrc = ((tid < 128) ? Whi : Wlo) + (size_t)bn * Kpad + bkh;
    __nv_bfloat16* bdst = ((tid < 128) ? sBhi : sBlo) + bn * ASTR + bkh;

    int lrow = w * 16 + (lane & 7) + ((lane >> 3) & 1) * 8;
    int lcol = (lane >> 4) * 8;
    uint32_t aoff = (uint32_t)(lrow * ASTR + lcol) * 2;
    uint32_t boff = (uint32_t)(g * ASTR + 2 * tg) * 2;

    float d[8][4];
#pragma unroll
    for (int i = 0; i < 8; i++)
#pragma unroll
        for (int j = 0; j < 4; j++) d[i][j] = 0.0f;

    float4 ra[8];
    uint4  rb[4];
    int nchunks = Kpad / KC;

    // prefetch chunk 0
    {
#pragma unroll
        for (int j = 0; j < 8; j++) {
            int k = akh + j * 4;
            ra[j] = (aOK && (k + 4 <= K)) ? *(const float4*)(xrow + k)
                                          : make_float4(0.f, 0.f, 0.f, 0.f);
        }
        const uint4* s = (const uint4*)bsrc;
#pragma unroll
        for (int q = 0; q < 4; q++) rb[q] = s[q];
    }

    for (int ch = 0; ch < nchunks; ch++) {
        // ---- convert/stage current chunk from regs to smem ----
        {
            uint32_t hi[16], lo[16];
#pragma unroll
            for (int j = 0; j < 8; j++) {
                float v0 = ra[j].x, v1 = ra[j].y, v2 = ra[j].z, v3 = ra[j].w;
                __nv_bfloat16 h0 = __float2bfloat16_rn(v0), h1 = __float2bfloat16_rn(v1);
                __nv_bfloat16 h2 = __float2bfloat16_rn(v2), h3 = __float2bfloat16_rn(v3);
                __nv_bfloat162 p01 = __halves2bfloat162(h0, h1);
                __nv_bfloat162 p23 = __halves2bfloat162(h2, h3);
                hi[2 * j]     = *(uint32_t*)&p01;
                hi[2 * j + 1] = *(uint32_t*)&p23;
                __nv_bfloat162 l01 = __halves2bfloat162(
                    __float2bfloat16_rn(v0 - __bfloat162float(h0)),
                    __float2bfloat16_rn(v1 - __bfloat162float(h1)));
                __nv_bfloat162 l23 = __halves2bfloat162(
                    __float2bfloat16_rn(v2 - __bfloat162float(h2)),
                    __float2bfloat16_rn(v3 - __bfloat162float(h3)));
                lo[2 * j]     = *(uint32_t*)&l01;
                lo[2 * j + 1] = *(uint32_t*)&l23;
            }
            uint32_t off = (uint32_t)(arow * ASTR + akh);
            uint4* dh = (uint4*)(sAhi + off);
            uint4* dl = (uint4*)(sAlo + off);
#pragma unroll
            for (int q = 0; q < 4; q++) {
                dh[q] = make_uint4(hi[4 * q], hi[4 * q + 1], hi[4 * q + 2], hi[4 * q + 3]);
                dl[q] = make_uint4(lo[4 * q], lo[4 * q + 1], lo[4 * q + 2], lo[4 * q + 3]);
            }
            uint4* dq = (uint4*)bdst;
#pragma unroll
            for (int q = 0; q < 4; q++) dq[q] = rb[q];
        }
        __syncthreads();

        // ---- prefetch next chunk into registers (overlaps with MMA) ----
        if (ch + 1 < nchunks) {
            int k0 = (ch + 1) * KC;
#pragma unroll
            for (int j = 0; j < 8; j++) {
                int k = k0 + akh + j * 4;
                ra[j] = (aOK && (k + 4 <= K)) ? *(const float4*)(xrow + k)
                                              : make_float4(0.f, 0.f, 0.f, 0.f);
            }
            const uint4* s = (const uint4*)(bsrc + k0);
#pragma unroll
            for (int q = 0; q < 4; q++) rb[q] = s[q];
        }

        // ---- MMA ----
#pragma unroll
        for (int ks = 0; ks < KC / 16; ks++) {
            uint32_t ah[4], al[4];
            ldm_x4(ah, uAhi + aoff + ks * 32);
            ldm_x4(al, uAlo + aoff + ks * 32);
            const char* bhP = (const char*)sBhi + boff + ks * 32;
            const char* blP = (const char*)sBlo + boff + ks * 32;
#pragma unroll
            for (int nt = 0; nt < 8; nt++) {
                uint32_t bh[2], bl[2];
                bh[0] = *(const uint32_t*)(bhP + nt * (8 * ASTR * 2));
                bh[1] = *(const uint32_t*)(bhP + nt * (8 * ASTR * 2) + 16);
                bl[0] = *(const uint32_t*)(blP + nt * (8 * ASTR * 2));
                bl[1] = *(const uint32_t*)(blP + nt * (8 * ASTR * 2) + 16);
                mma_bf16(d[nt], ah, bh);
                mma_bf16(d[nt], al, bh);
                mma_bf16(d[nt], ah, bl);
            }
        }
        __syncthreads();
    }

    // ---- epilogue: y = xw*dinv; write y and acc(=self-loop y) ----
#pragma unroll
    for (int rs = 0; rs < 2; rs++) {
        int row = blockIdx.x * 128 + w * 16 + g + rs * 8;
        if (row < M) {
            float dv = dinv[row];
            float* yp = Y + (size_t)row * 64;
            float* ac = ACC + (size_t)row * 64;
#pragma unroll
            for (int nt = 0; nt < 8; nt++) {
                int col = nt * 8 + 2 * tg;
                float2 v = make_float2(d[nt][2 * rs] * dv, d[nt][2 * rs + 1] * dv);
                *(float2*)(yp + col) = v;
                *(float2*)(ac + col) = v;
            }
        }
    }
}

// ---------------------------------------------------------------------------
// edge scatter: acc[dst] += y[src]; 16 thr/edge, v4 red (no norm math needed)
// ---------------------------------------------------------------------------
__global__ void k_scatter(const int* __restrict__ src, const int* __restrict__ dst,
                          const float* __restrict__ y, float* __restrict__ acc, int E) {
    int t = blockIdx.x * blockDim.x + threadIdx.x;
    int e = t >> 4;
    int f4 = t & 15;
    if (e < E) {
        int s = src[e], d = dst[e];
        float4 v = *(const float4*)(y + (size_t)s * 64 + f4 * 4);
        float* o = acc + (size_t)d * 64 + f4 * 4;
        asm volatile("red.global.add.v4.f32 [%0], {%1,%2,%3,%4};"
                     :: "l"(o), "f"(v.x), "f"(v.y), "f"(v.z), "f"(v.w)
                     : "memory");
    }
}

// ---------------------------------------------------------------------------
// pool: relu(dinv[n]*acc[n][f] + b[f]) accumulated per sorted-batch run
// ---------------------------------------------------------------------------
#define POOL_CH 256
__global__ __launch_bounds__(256) void k_pool(const float* __restrict__ acc,
                                              const int* __restrict__ batch,
                                              const float* __restrict__ bias,
                                              const float* __restrict__ dinv,
                                              int n, int colbase, int cntbase) {
    int f = threadIdx.x & 63;
    int grp = threadIdx.x >> 6;
    int n0 = blockIdx.x * POOL_CH;
    int nend = min(n0 + POOL_CH, n);
    float b = bias[f];
    float sum = 0.0f, cnt = 0.0f;
    int curg = -1;
    for (int nn = n0 + grp; nn < nend; nn += 4) {
        int g = batch[nn];
        if (g != curg) {
            if (curg >= 0) {
                atomicAdd(&g_pool[curg * 128 + colbase + f], sum);
                if (f == 0) atomicAdd(&g_cnt[cntbase + curg], cnt);
            }
            curg = g; sum = 0.0f; cnt = 0.0f;
        }
        float v = dinv[nn] * acc[(size_t)nn * 64 + f] + b;
        sum += fmaxf(v, 0.0f);
        cnt += 1.0f;
    }
    if (curg >= 0) {
        atomicAdd(&g_pool[curg * 128 + colbase + f], sum);
        if (f == 0) atomicAdd(&g_cnt[cntbase + curg], cnt);
    }
}

__global__ void k_final(const float* __restrict__ linW, const float* __restrict__ linb,
                        float* __restrict__ out) {
    int t = threadIdx.x;
    int g = t >> 1, c = t & 1;
    float cp = fmaxf(g_cnt[g], 1.0f);
    float cr = fmaxf(g_cnt[NG + g], 1.0f);
    float s = linb[c];
#pragma unroll 8
    for (int j = 0; j < 64; j++)  s += (g_pool[g * 128 + j] / cp) * linW[j * 2 + c];
#pragma unroll 8
    for (int j = 64; j < 128; j++) s += (g_pool[g * 128 + j] / cr) * linW[j * 2 + c];
    out[g * 2 + c] = s;
}

// ---------------------------------------------------------------------------
extern "C" void kernel_launch(void* const* d_in, const int* in_sizes, int n_in,
                              void* d_out, int out_size) {
    const float* p_x   = (const float*)d_in[0];
    const int*   p_ei  = (const int*)d_in[1];
    const int*   p_bat = (const int*)d_in[2];
    const float* r_x   = (const float*)d_in[3];
    const int*   r_ei  = (const int*)d_in[4];
    const int*   r_bat = (const int*)d_in[5];
    const float* p_W   = (const float*)d_in[6];
    const float* p_b   = (const float*)d_in[7];
    const float* r_W   = (const float*)d_in[8];
    const float* r_b   = (const float*)d_in[9];
    const float* linW  = (const float*)d_in[10];
    const float* linb  = (const float*)d_in[11];
    float* out = (float*)d_out;

    int Np = in_sizes[2];
    int Kp = in_sizes[0] / Np;
    int Ep = in_sizes[1] / 2;
    int Nr = in_sizes[5];
    int Kr = in_sizes[3] / Nr;
    int Er = in_sizes[4] / 2;
    int KpPad = ((Kp + 63) / 64) * 64;
    int KrPad = ((Kr + 63) / 64) * 64;

    float *p_y, *r_y, *p_acc, *r_acc, *p_dinv, *r_dinv;
    __nv_bfloat16 *pWhi, *pWlo, *rWhi, *rWlo;
    cudaGetSymbolAddress((void**)&p_y, g_p_y);
    cudaGetSymbolAddress((void**)&r_y, g_r_y);
    cudaGetSymbolAddress((void**)&p_acc, g_p_acc);
    cudaGetSymbolAddress((void**)&r_acc, g_r_acc);
    cudaGetSymbolAddress((void**)&p_dinv, g_p_dinv);
    cudaGetSymbolAddress((void**)&r_dinv, g_r_dinv);
    cudaGetSymbolAddress((void**)&pWhi, g_pWhi);
    cudaGetSymbolAddress((void**)&pWlo, g_pWlo);
    cudaGetSymbolAddress((void**)&rWhi, g_rWhi);
    cudaGetSymbolAddress((void**)&rWlo, g_rWlo);

    static int smem_set = 0;
    int smem_bytes = (2 * SZ_A + 2 * SZ_B) * 2;
    if (!smem_set) {
        cudaFuncSetAttribute(k_gemm_mma, cudaFuncAttributeMaxDynamicSharedMemorySize, smem_bytes);
        smem_set = 1;
    }

    int nmax = (Np > Nr ? Np : Nr);
    if (nmax < NG * 128) nmax = NG * 128;
    if (nmax < 64 * KpPad) nmax = 64 * KpPad;
    if (nmax < 64 * KrPad) nmax = 64 * KrPad;

    // launches 1-5 (so that launch 6 = p-branch GEMM gets ncu'd with -s 5 -c 1)
    k_init<<<(nmax + 255) / 256, 256>>>(Np, Nr, p_W, r_W, Kp, KpPad, Kr, KrPad);
    k_count<<<(Ep + 255) / 256, 256>>>(p_ei + Ep, Ep, p_dinv);
    k_count<<<(Er + 255) / 256, 256>>>(r_ei + Er, Er, r_dinv);
    k_dinv<<<(Np + 255) / 256, 256>>>(p_dinv, Np);
    k_dinv<<<(Nr + 255) / 256, 256>>>(r_dinv, Nr);

    // launch 6: the big GEMM
    k_gemm_mma<<<(Np + 127) / 128, 256, smem_bytes>>>(p_x, pWhi, pWlo, p_dinv, p_y, p_acc, Np, Kp, KpPad);
    k_gemm_mma<<<(Nr + 127) / 128, 256, smem_bytes>>>(r_x, rWhi, rWlo, r_dinv, r_y, r_acc, Nr, Kr, KrPad);

    {
        long long tp = (long long)Ep * 16;
        k_scatter<<<(unsigned)((tp + 255) / 256), 256>>>(p_ei, p_ei + Ep, p_y, p_acc, Ep);
        long long tr = (long long)Er * 16;
        k_scatter<<<(unsigned)((tr + 255) / 256), 256>>>(r_ei, r_ei + Er, r_y, r_acc, Er);
    }

    k_pool<<<(Np + POOL_CH - 1) / POOL_CH, 256>>>(p_acc, p_bat, p_b, p_dinv, Np, 0, 0);
    k_pool<<<(Nr + POOL_CH - 1) / POOL_CH, 256>>>(r_acc, r_bat, r_b, r_dinv, Nr, 64, NG);

    k_final<<<1, 256>>>(linW, linb, out);
}

// round 5
// speedup vs baseline: 1.0609x; 1.0609x over previous
#include <cuda_runtime.h>
#include <cuda_bf16.h>
#include <cstdint>

#define NG 128
#define NPMAX 200000
#define NRMAX 400000

// ---- static scratch ----
__device__ __align__(16) float g_p_y  [NPMAX * 64];
__device__ __align__(16) float g_r_y  [NRMAX * 64];
__device__ __align__(16) float g_p_acc[NPMAX * 64];
__device__ __align__(16) float g_r_acc[NRMAX * 64];
__device__ float g_p_deg[NPMAX];
__device__ float g_r_deg[NRMAX];
__device__ float g_pool[NG * 128];
__device__ float g_cnt[2 * NG];
__device__ __align__(16) __nv_bfloat16 g_pWhi[64 * 1280];
__device__ __align__(16) __nv_bfloat16 g_pWlo[64 * 1280];
__device__ __align__(16) __nv_bfloat16 g_rWhi[64 * 128];
__device__ __align__(16) __nv_bfloat16 g_rWlo[64 * 128];

__device__ __forceinline__ uint32_t smem_u32(const void* p) {
    uint32_t a;
    asm("{ .reg .u64 t; cvta.to.shared.u64 t, %1; cvt.u32.u64 %0, t; }" : "=r"(a) : "l"(p));
    return a;
}

__device__ __forceinline__ void ldm_x4(uint32_t* r, uint32_t addr) {
    asm volatile("ldmatrix.sync.aligned.m8n8.x4.shared.b16 {%0,%1,%2,%3}, [%4];"
                 : "=r"(r[0]), "=r"(r[1]), "=r"(r[2]), "=r"(r[3]) : "r"(addr));
}

__device__ __forceinline__ void mma_bf16(float* d, const uint32_t* a, uint32_t b0, uint32_t b1) {
    asm volatile(
        "mma.sync.aligned.m16n8k16.row.col.f32.bf16.bf16.f32 "
        "{%0,%1,%2,%3}, {%4,%5,%6,%7}, {%8,%9}, {%0,%1,%2,%3};"
        : "+f"(d[0]), "+f"(d[1]), "+f"(d[2]), "+f"(d[3])
        : "r"(a[0]), "r"(a[1]), "r"(a[2]), "r"(a[3]), "r"(b0), "r"(b1));
}

// ---------------------------------------------------------------------------
// init (deg=1 self loop, pool/cnt=0) + W hi/lo split, fused
// ---------------------------------------------------------------------------
__global__ void k_init(int np, int nr,
                       const float* __restrict__ pW, const float* __restrict__ rW,
                       int Kp, int KpPad, int Kr, int KrPad) {
    int i = blockIdx.x * blockDim.x + threadIdx.x;
    if (i < np) g_p_deg[i] = 1.0f;
    if (i < nr) g_r_deg[i] = 1.0f;
    if (i < NG * 128) g_pool[i] = 0.0f;
    if (i < 2 * NG) g_cnt[i] = 0.0f;
    if (i < 64 * KpPad) {
        int n = i / KpPad, k = i % KpPad;
        float v = (k < Kp) ? pW[k * 64 + n] : 0.0f;
        __nv_bfloat16 h = __float2bfloat16_rn(v);
        g_pWhi[i] = h;
        g_pWlo[i] = __float2bfloat16_rn(v - __bfloat162float(h));
    }
    if (i < 64 * KrPad) {
        int n = i / KrPad, k = i % KrPad;
        float v = (k < Kr) ? rW[k * 64 + n] : 0.0f;
        __nv_bfloat16 h = __float2bfloat16_rn(v);
        g_rWhi[i] = h;
        g_rWlo[i] = __float2bfloat16_rn(v - __bfloat162float(h));
    }
}

__global__ void k_count(const int* __restrict__ dst, int E, float* __restrict__ deg) {
    int e = blockIdx.x * blockDim.x + threadIdx.x;
    if (e < E) atomicAdd(&deg[dst[e]], 1.0f);
}

// ---------------------------------------------------------------------------
// HMMA GEMM, bf16x3 (A hi/lo, W hi/lo; ah*bh + al*bh + ah*bl).
// CTA: 128 rows x 64 cols, 256 threads. B-fragments via ldmatrix.x4.
// Epilogue: y = xw * rsqrt(deg); writes Y and ACC (self-loop term).
// ---------------------------------------------------------------------------
#define KC 64
#define APAD 8
#define ASTR (KC + APAD)
#define SZ_A (128 * ASTR)
#define SZ_B (64 * ASTR)
extern __shared__ __align__(16) __nv_bfloat16 dynsm[];

__global__ __launch_bounds__(256) void k_gemm_mma(
    const float* __restrict__ X,
    const __nv_bfloat16* __restrict__ Whi, const __nv_bfloat16* __restrict__ Wlo,
    const float* __restrict__ deg,
    float* __restrict__ Y, float* __restrict__ ACC,
    int M, int K, int Kpad)
{
    __nv_bfloat16* sAhi = dynsm;
    __nv_bfloat16* sAlo = dynsm + SZ_A;
    __nv_bfloat16* sBhi = dynsm + 2 * SZ_A;
    __nv_bfloat16* sBlo = dynsm + 2 * SZ_A + SZ_B;
    uint32_t uAhi = smem_u32(sAhi), uAlo = smem_u32(sAlo);
    uint32_t uBhi = smem_u32(sBhi), uBlo = smem_u32(sBlo);

    int tid = threadIdx.x;
    int w = tid >> 5, lane = tid & 31;
    int g = lane >> 2, tg = lane & 3;

    // A loader: thread t -> row t/2, k-half (t&1)*32
    int arow = tid >> 1;
    int akh  = (tid & 1) * 32;
    int grow = blockIdx.x * 128 + arow;
    bool aOK = grow < M;
    const float* xrow = X + (size_t)grow * K;

    // B loader: t<128 -> hi, t>=128 -> lo
    int bt = tid & 127;
    int bn = bt >> 1;
    int bkh = (bt & 1) * 32;
    const __nv_bfloat16* bsrc = ((tid < 128) ? Whi : Wlo) + (size_t)bn * Kpad + bkh;
    __nv_bfloat16* bdst = ((tid < 128) ? sBhi : sBlo) + bn * ASTR + bkh;

    // A-frag ldmatrix per-lane offset
    int lrow = w * 16 + (lane & 7) + ((lane >> 3) & 1) * 8;
    int lcol = (lane >> 4) * 8;
    uint32_t aoff = (uint32_t)(lrow * ASTR + lcol) * 2;

    // B-frag ldmatrix.x4 per-lane offset: tile t=lane/8 ->
    //   n = (t>>1)*8 + (lane&7), k = (t&1)*8
    {
    }
    int bTile = lane >> 3;
    uint32_t bfoff = (uint32_t)(((bTile >> 1) * 8 + (lane & 7)) * ASTR + (bTile & 1) * 8) * 2;

    float d[8][4];
#pragma unroll
    for (int i = 0; i < 8; i++)
#pragma unroll
        for (int j = 0; j < 4; j++) d[i][j] = 0.0f;

    int nchunks = Kpad / KC;
    for (int ch = 0; ch < nchunks; ch++) {
        int k0 = ch * KC;
        if (ch > 0) __syncthreads();

        // ---- stage A (fp32 -> hi/lo bf16) ----
        {
            uint32_t hi[16], lo[16];
#pragma unroll
            for (int j = 0; j < 8; j++) {
                int k = k0 + akh + j * 4;
                float4 t = (aOK && (k + 4 <= K)) ? *(const float4*)(xrow + k)
                                                 : make_float4(0.f, 0.f, 0.f, 0.f);
                float v0 = t.x, v1 = t.y, v2 = t.z, v3 = t.w;
                __nv_bfloat16 h0 = __float2bfloat16_rn(v0), h1 = __float2bfloat16_rn(v1);
                __nv_bfloat16 h2 = __float2bfloat16_rn(v2), h3 = __float2bfloat16_rn(v3);
                __nv_bfloat162 p01 = __halves2bfloat162(h0, h1);
                __nv_bfloat162 p23 = __halves2bfloat162(h2, h3);
                hi[2 * j]     = *(uint32_t*)&p01;
                hi[2 * j + 1] = *(uint32_t*)&p23;
                __nv_bfloat162 l01 = __halves2bfloat162(
                    __float2bfloat16_rn(v0 - __bfloat162float(h0)),
                    __float2bfloat16_rn(v1 - __bfloat162float(h1)));
                __nv_bfloat162 l23 = __halves2bfloat162(
                    __float2bfloat16_rn(v2 - __bfloat162float(h2)),
                    __float2bfloat16_rn(v3 - __bfloat162float(h3)));
                lo[2 * j]     = *(uint32_t*)&l01;
                lo[2 * j + 1] = *(uint32_t*)&l23;
            }
            uint32_t off = (uint32_t)(arow * ASTR + akh);
            uint4* dh = (uint4*)(sAhi + off);
            uint4* dl = (uint4*)(sAlo + off);
#pragma unroll
            for (int q = 0; q < 4; q++) {
                dh[q] = make_uint4(hi[4 * q], hi[4 * q + 1], hi[4 * q + 2], hi[4 * q + 3]);
                dl[q] = make_uint4(lo[4 * q], lo[4 * q + 1], lo[4 * q + 2], lo[4 * q + 3]);
            }
        }
        // ---- stage B ----
        {
            const uint4* s = (const uint4*)(bsrc + k0);
            uint4* dq = (uint4*)bdst;
#pragma unroll
            for (int q = 0; q < 4; q++) dq[q] = s[q];
        }
        __syncthreads();

        // ---- MMA ----
#pragma unroll
        for (int ks = 0; ks < KC / 16; ks++) {
            uint32_t ah[4], al[4];
            ldm_x4(ah, uAhi + aoff + ks * 32);
            ldm_x4(al, uAlo + aoff + ks * 32);
#pragma unroll
            for (int np = 0; np < 4; np++) {
                uint32_t boffc = bfoff + (uint32_t)(np * 16 * ASTR + ks * 16) * 2;
                uint32_t bh[4], bl[4];
                ldm_x4(bh, uBhi + boffc);
                ldm_x4(bl, uBlo + boffc);
                mma_bf16(d[np * 2],     ah, bh[0], bh[1]);
                mma_bf16(d[np * 2],     al, bh[0], bh[1]);
                mma_bf16(d[np * 2],     ah, bl[0], bl[1]);
                mma_bf16(d[np * 2 + 1], ah, bh[2], bh[3]);
                mma_bf16(d[np * 2 + 1], al, bh[2], bh[3]);
                mma_bf16(d[np * 2 + 1], ah, bl[2], bl[3]);
            }
        }
    }

    // ---- epilogue: y = xw * rsqrt(deg); write Y and ACC ----
#pragma unroll
    for (int rs = 0; rs < 2; rs++) {
        int row = blockIdx.x * 128 + w * 16 + g + rs * 8;
        if (row < M) {
            float dv = rsqrtf(deg[row]);
            float* yp = Y + (size_t)row * 64;
            float* ac = ACC + (size_t)row * 64;
#pragma unroll
            for (int nt = 0; nt < 8; nt++) {
                int col = nt * 8 + 2 * tg;
                float2 v = make_float2(d[nt][2 * rs] * dv, d[nt][2 * rs + 1] * dv);
                *(float2*)(yp + col) = v;
                *(float2*)(ac + col) = v;
            }
        }
    }
}

// ---------------------------------------------------------------------------
// edge scatter: acc[dst] += y[src]; 16 thr/edge, v4 red
// ---------------------------------------------------------------------------
__global__ void k_scatter(const int* __restrict__ src, const int* __restrict__ dst,
                          const float* __restrict__ y, float* __restrict__ acc, int E) {
    int t = blockIdx.x * blockDim.x + threadIdx.x;
    int e = t >> 4;
    int f4 = t & 15;
    if (e < E) {
        int s = src[e], d = dst[e];
        float4 v = *(const float4*)(y + (size_t)s * 64 + f4 * 4);
        float* o = acc + (size_t)d * 64 + f4 * 4;
        asm volatile("red.global.add.v4.f32 [%0], {%1,%2,%3,%4};"
                     :: "l"(o), "f"(v.x), "f"(v.y), "f"(v.z), "f"(v.w)
                     : "memory");
    }
}

// ---------------------------------------------------------------------------
// pool: relu(rsqrt(deg[n])*acc[n][f] + b[f]) accumulated per sorted-batch run
// ---------------------------------------------------------------------------
#define POOL_CH 256
__global__ __launch_bounds__(256) void k_pool(const float* __restrict__ acc,
                                              const int* __restrict__ batch,
                                              const float* __restrict__ bias,
                                              const float* __restrict__ deg,
                                              int n, int colbase, int cntbase) {
    int f = threadIdx.x & 63;
    int grp = threadIdx.x >> 6;
    int n0 = blockIdx.x * POOL_CH;
    int nend = min(n0 + POOL_CH, n);
    float b = bias[f];
    float sum = 0.0f, cnt = 0.0f;
    int curg = -1;
    for (int nn = n0 + grp; nn < nend; nn += 4) {
        int g = batch[nn];
        if (g != curg) {
            if (curg >= 0) {
                atomicAdd(&g_pool[curg * 128 + colbase + f], sum);
                if (f == 0) atomicAdd(&g_cnt[cntbase + curg], cnt);
            }
            curg = g; sum = 0.0f; cnt = 0.0f;
        }
        float v = rsqrtf(deg[nn]) * acc[(size_t)nn * 64 + f] + b;
        sum += fmaxf(v, 0.0f);
        cnt += 1.0f;
    }
    if (curg >= 0) {
        atomicAdd(&g_pool[curg * 128 + colbase + f], sum);
        if (f == 0) atomicAdd(&g_cnt[cntbase + curg], cnt);
    }
}

__global__ void k_final(const float* __restrict__ linW, const float* __restrict__ linb,
                        float* __restrict__ out) {
    int t = threadIdx.x;
    int g = t >> 1, c = t & 1;
    float cp = fmaxf(g_cnt[g], 1.0f);
    float cr = fmaxf(g_cnt[NG + g], 1.0f);
    float s = linb[c];
#pragma unroll 8
    for (int j = 0; j < 64; j++)  s += (g_pool[g * 128 + j] / cp) * linW[j * 2 + c];
#pragma unroll 8
    for (int j = 64; j < 128; j++) s += (g_pool[g * 128 + j] / cr) * linW[j * 2 + c];
    out[g * 2 + c] = s;
}

// ---------------------------------------------------------------------------
extern "C" void kernel_launch(void* const* d_in, const int* in_sizes, int n_in,
                              void* d_out, int out_size) {
    const float* p_x   = (const float*)d_in[0];
    const int*   p_ei  = (const int*)d_in[1];
    const int*   p_bat = (const int*)d_in[2];
    const float* r_x   = (const float*)d_in[3];
    const int*   r_ei  = (const int*)d_in[4];
    const int*   r_bat = (const int*)d_in[5];
    const float* p_W   = (const float*)d_in[6];
    const float* p_b   = (const float*)d_in[7];
    const float* r_W   = (const float*)d_in[8];
    const float* r_b   = (const float*)d_in[9];
    const float* linW  = (const float*)d_in[10];
    const float* linb  = (const float*)d_in[11];
    float* out = (float*)d_out;

    int Np = in_sizes[2];
    int Kp = in_sizes[0] / Np;
    int Ep = in_sizes[1] / 2;
    int Nr = in_sizes[5];
    int Kr = in_sizes[3] / Nr;
    int Er = in_sizes[4] / 2;
    int KpPad = ((Kp + 63) / 64) * 64;
    int KrPad = ((Kr + 63) / 64) * 64;

    float *p_y, *r_y, *p_acc, *r_acc, *p_deg, *r_deg;
    __nv_bfloat16 *pWhi, *pWlo, *rWhi, *rWlo;
    cudaGetSymbolAddress((void**)&p_y, g_p_y);
    cudaGetSymbolAddress((void**)&r_y, g_r_y);
    cudaGetSymbolAddress((void**)&p_acc, g_p_acc);
    cudaGetSymbolAddress((void**)&r_acc, g_r_acc);
    cudaGetSymbolAddress((void**)&p_deg, g_p_deg);
    cudaGetSymbolAddress((void**)&r_deg, g_r_deg);
    cudaGetSymbolAddress((void**)&pWhi, g_pWhi);
    cudaGetSymbolAddress((void**)&pWlo, g_pWlo);
    cudaGetSymbolAddress((void**)&rWhi, g_rWhi);
    cudaGetSymbolAddress((void**)&rWlo, g_rWlo);

    static int smem_set = 0;
    int smem_bytes = (2 * SZ_A + 2 * SZ_B) * 2;
    if (!smem_set) {
        cudaFuncSetAttribute(k_gemm_mma, cudaFuncAttributeMaxDynamicSharedMemorySize, smem_bytes);
        smem_set = 1;
    }

    int nmax = (Np > Nr ? Np : Nr);
    if (nmax < NG * 128) nmax = NG * 128;
    if (nmax < 64 * KpPad) nmax = 64 * KpPad;
    if (nmax < 64 * KrPad) nmax = 64 * KrPad;

    // launch 1-3
    k_init<<<(nmax + 255) / 256, 256>>>(Np, Nr, p_W, r_W, Kp, KpPad, Kr, KrPad);
    k_count<<<(Ep + 255) / 256, 256>>>(p_ei + Ep, Ep, p_deg);
    k_count<<<(Er + 255) / 256, 256>>>(r_ei + Er, Er, r_deg);

    // launch 4: p-branch GEMM (lands in the profiled slot)
    k_gemm_mma<<<(Np + 127) / 128, 256, smem_bytes>>>(p_x, pWhi, pWlo, p_deg, p_y, p_acc, Np, Kp, KpPad);
    k_gemm_mma<<<(Nr + 127) / 128, 256, smem_bytes>>>(r_x, rWhi, rWlo, r_deg, r_y, r_acc, Nr, Kr, KrPad);

    {
        long long tp = (long long)Ep * 16;
        k_scatter<<<(unsigned)((tp + 255) / 256), 256>>>(p_ei, p_ei + Ep, p_y, p_acc, Ep);
        long long tr = (long long)Er * 16;
        k_scatter<<<(unsigned)((tr + 255) / 256), 256>>>(r_ei, r_ei + Er, r_y, r_acc, Er);
    }

    k_pool<<<(Np + POOL_CH - 1) / POOL_CH, 256>>>(p_acc, p_bat, p_b, p_deg, Np, 0, 0);
    k_pool<<<(Nr + POOL_CH - 1) / POOL_CH, 256>>>(r_acc, r_bat, r_b, r_deg, Nr, 64, NG);

    k_final<<<1, 256>>>(linW, linb, out);
}

// round 6
// speedup vs baseline: 1.2156x; 1.1458x over previous
#include <cuda_runtime.h>
#include <cuda_bf16.h>
#include <cstdint>

#define NG 128
#define NPMAX 200000
#define NRMAX 400000

// ---- static scratch ----
__device__ __align__(16) float g_p_y  [NPMAX * 64];
__device__ __align__(16) float g_r_y  [NRMAX * 64];
__device__ __align__(16) float g_p_acc[NPMAX * 64];
__device__ __align__(16) float g_r_acc[NRMAX * 64];
__device__ float g_p_deg[NPMAX];
__device__ float g_r_deg[NRMAX];
__device__ float g_pool[NG * 128];
__device__ float g_cnt[2 * NG];
__device__ __align__(16) __nv_bfloat16 g_pWhi[64 * 1280];
__device__ __align__(16) __nv_bfloat16 g_pWlo[64 * 1280];
__device__ __align__(16) __nv_bfloat16 g_rWhi[64 * 128];
__device__ __align__(16) __nv_bfloat16 g_rWlo[64 * 128];

__device__ __forceinline__ uint32_t smem_u32(const void* p) {
    uint32_t a;
    asm("{ .reg .u64 t; cvta.to.shared.u64 t, %1; cvt.u32.u64 %0, t; }" : "=r"(a) : "l"(p));
    return a;
}

__device__ __forceinline__ void ldm_x4(uint32_t* r, uint32_t addr) {
    asm volatile("ldmatrix.sync.aligned.m8n8.x4.shared.b16 {%0,%1,%2,%3}, [%4];"
                 : "=r"(r[0]), "=r"(r[1]), "=r"(r[2]), "=r"(r[3]) : "r"(addr));
}

__device__ __forceinline__ void mma_bf16(float* d, const uint32_t* a, uint32_t b0, uint32_t b1) {
    asm volatile(
        "mma.sync.aligned.m16n8k16.row.col.f32.bf16.bf16.f32 "
        "{%0,%1,%2,%3}, {%4,%5,%6,%7}, {%8,%9}, {%0,%1,%2,%3};"
        : "+f"(d[0]), "+f"(d[1]), "+f"(d[2]), "+f"(d[3])
        : "r"(a[0]), "r"(a[1]), "r"(a[2]), "r"(a[3]), "r"(b0), "r"(b1));
}

// fp32 pair -> (hi bf16x2, lo bf16x2)
__device__ __forceinline__ void cvt_hilo(float x, float y, uint32_t& hi, uint32_t& lo) {
    __nv_bfloat162 h = __float22bfloat162_rn(make_float2(x, y));
    float hx = __low2float(h), hy = __high2float(h);
    __nv_bfloat162 l = __float22bfloat162_rn(make_float2(x - hx, y - hy));
    hi = *(uint32_t*)&h;
    lo = *(uint32_t*)&l;
}

// ---------------------------------------------------------------------------
// init (deg=1 self loop, pool/cnt=0) + W hi/lo split, fused
// ---------------------------------------------------------------------------
__global__ void k_init(int np, int nr,
                       const float* __restrict__ pW, const float* __restrict__ rW,
                       int Kp, int KpPad, int Kr, int KrPad) {
    int i = blockIdx.x * blockDim.x + threadIdx.x;
    if (i < np) g_p_deg[i] = 1.0f;
    if (i < nr) g_r_deg[i] = 1.0f;
    if (i < NG * 128) g_pool[i] = 0.0f;
    if (i < 2 * NG) g_cnt[i] = 0.0f;
    if (i < 64 * KpPad) {
        int n = i / KpPad, k = i % KpPad;
        float v = (k < Kp) ? pW[k * 64 + n] : 0.0f;
        __nv_bfloat16 h = __float2bfloat16_rn(v);
        g_pWhi[i] = h;
        g_pWlo[i] = __float2bfloat16_rn(v - __bfloat162float(h));
    }
    if (i < 64 * KrPad) {
        int n = i / KrPad, k = i % KrPad;
        float v = (k < Kr) ? rW[k * 64 + n] : 0.0f;
        __nv_bfloat16 h = __float2bfloat16_rn(v);
        g_rWhi[i] = h;
        g_rWlo[i] = __float2bfloat16_rn(v - __bfloat162float(h));
    }
}

__global__ void k_count(const int* __restrict__ dst, int E, float* __restrict__ deg) {
    int e = blockIdx.x * blockDim.x + threadIdx.x;
    if (e < E) atomicAdd(&deg[dst[e]], 1.0f);
}

// ---------------------------------------------------------------------------
// HMMA GEMM, bf16x3. CTA tile 256x64, 8 warps, warp tile m32 x n64.
// A fragments loaded DIRECTLY from global into registers (no smem round trip).
// B (hi/lo) staged in smem per K-chunk, consumed via ldmatrix.x4.
// Epilogue: y = xw * rsqrt(deg); writes Y and ACC (self-loop term).
// ---------------------------------------------------------------------------
#define KC 64
#define BPAD 8
#define BSTR (KC + BPAD)   // 72 bf16 per B row

__global__ __launch_bounds__(256, 1) void k_gemm_mma(
    const float* __restrict__ X,
    const __nv_bfloat16* __restrict__ Whi, const __nv_bfloat16* __restrict__ Wlo,
    const float* __restrict__ deg,
    float* __restrict__ Y, float* __restrict__ ACC,
    int M, int K, int Kpad)
{
    __shared__ __align__(16) __nv_bfloat16 sBhi[64 * BSTR];
    __shared__ __align__(16) __nv_bfloat16 sBlo[64 * BSTR];
    uint32_t uBhi = smem_u32(sBhi), uBlo = smem_u32(sBlo);

    int tid = threadIdx.x;
    int w = tid >> 5, lane = tid & 31;
    int g = lane >> 2, tg = lane & 3;

    // B loader: t<128 -> hi, t>=128 -> lo; n=(t&127)/2, k-half
    int bt = tid & 127;
    int bn = bt >> 1;
    int bkh = (bt & 1) * 32;
    const __nv_bfloat16* bsrc = ((tid < 128) ? Whi : Wlo) + (size_t)bn * Kpad + bkh;
    __nv_bfloat16* bdst = ((tid < 128) ? sBhi : sBlo) + bn * BSTR + bkh;

    // B-frag ldmatrix.x4 per-lane offset (tile bTile = lane/8):
    //   n = (bTile>>1)*8 + (lane&7), k = (bTile&1)*8
    int bTile = lane >> 3;
    uint32_t bfoff = (uint32_t)(((bTile >> 1) * 8 + (lane & 7)) * BSTR + (bTile & 1) * 8) * 2;

    // A rows for this warp (m32: two m16 slabs)
    int rowBase = blockIdx.x * 256 + w * 32;
    int r0[2], r1[2];
    bool ok0[2], ok1[2];
#pragma unroll
    for (int mt = 0; mt < 2; mt++) {
        r0[mt] = rowBase + mt * 16 + g;
        r1[mt] = r0[mt] + 8;
        ok0[mt] = r0[mt] < M;
        ok1[mt] = r1[mt] < M;
    }
    const float* xr0[2] = { X + (size_t)r0[0] * K, X + (size_t)r0[1] * K };
    const float* xr1[2] = { X + (size_t)r1[0] * K, X + (size_t)r1[1] * K };

    float d[2][8][4];
#pragma unroll
    for (int mt = 0; mt < 2; mt++)
#pragma unroll
        for (int nt = 0; nt < 8; nt++)
#pragma unroll
            for (int j = 0; j < 4; j++) d[mt][nt][j] = 0.0f;

    const float2 z2 = make_float2(0.f, 0.f);
    int nchunks = Kpad / KC;

    for (int ch = 0; ch < nchunks; ch++) {
        int k0 = ch * KC;
        if (ch > 0) __syncthreads();
        // ---- stage B chunk ----
        {
            const uint4* s = (const uint4*)(bsrc + k0);
            uint4* dq = (uint4*)bdst;
#pragma unroll
            for (int q = 0; q < 4; q++) dq[q] = s[q];
        }
        __syncthreads();

#pragma unroll
        for (int ks = 0; ks < KC / 16; ks++) {
            int kk = k0 + ks * 16 + tg * 2;
            bool kOK0 = (kk + 2) <= K;
            bool kOK1 = (kk + 10) <= K;

            // ---- A fragments direct from global ----
            uint32_t ah[2][4], al[2][4];
#pragma unroll
            for (int mt = 0; mt < 2; mt++) {
                float2 f00 = (ok0[mt] && kOK0) ? *(const float2*)(xr0[mt] + kk) : z2;
                float2 f10 = (ok1[mt] && kOK0) ? *(const float2*)(xr1[mt] + kk) : z2;
                float2 f01 = (ok0[mt] && kOK1) ? *(const float2*)(xr0[mt] + kk + 8) : z2;
                float2 f11 = (ok1[mt] && kOK1) ? *(const float2*)(xr1[mt] + kk + 8) : z2;
                cvt_hilo(f00.x, f00.y, ah[mt][0], al[mt][0]);
                cvt_hilo(f10.x, f10.y, ah[mt][1], al[mt][1]);
                cvt_hilo(f01.x, f01.y, ah[mt][2], al[mt][2]);
                cvt_hilo(f11.x, f11.y, ah[mt][3], al[mt][3]);
            }

            // ---- B fragments + MMA ----
#pragma unroll
            for (int np = 0; np < 4; np++) {
                uint32_t boffc = bfoff + (uint32_t)(np * 16 * BSTR + ks * 16) * 2;
                uint32_t bh[4], bl[4];
                ldm_x4(bh, uBhi + boffc);
                ldm_x4(bl, uBlo + boffc);
#pragma unroll
                for (int mt = 0; mt < 2; mt++) {
                    mma_bf16(d[mt][np * 2],     ah[mt], bh[0], bh[1]);
                    mma_bf16(d[mt][np * 2],     al[mt], bh[0], bh[1]);
                    mma_bf16(d[mt][np * 2],     ah[mt], bl[0], bl[1]);
                    mma_bf16(d[mt][np * 2 + 1], ah[mt], bh[2], bh[3]);
                    mma_bf16(d[mt][np * 2 + 1], al[mt], bh[2], bh[3]);
                    mma_bf16(d[mt][np * 2 + 1], ah[mt], bl[2], bl[3]);
                }
            }
        }
    }

    // ---- epilogue: y = xw * rsqrt(deg); write Y and ACC ----
#pragma unroll
    for (int mt = 0; mt < 2; mt++) {
#pragma unroll
        for (int rs = 0; rs < 2; rs++) {
            int row = rowBase + mt * 16 + g + rs * 8;
            if (row < M) {
                float dv = rsqrtf(deg[row]);
                float* yp = Y + (size_t)row * 64;
                float* ac = ACC + (size_t)row * 64;
#pragma unroll
                for (int nt = 0; nt < 8; nt++) {
                    int col = nt * 8 + 2 * tg;
                    float2 v = make_float2(d[mt][nt][2 * rs] * dv, d[mt][nt][2 * rs + 1] * dv);
                    *(float2*)(yp + col) = v;
                    *(float2*)(ac + col) = v;
                }
            }
        }
    }
}

// ---------------------------------------------------------------------------
// edge scatter: acc[dst] += y[src]; 16 thr/edge, v4 red
// ---------------------------------------------------------------------------
__global__ void k_scatter(const int* __restrict__ src, const int* __restrict__ dst,
                          const float* __restrict__ y, float* __restrict__ acc, int E) {
    int t = blockIdx.x * blockDim.x + threadIdx.x;
    int e = t >> 4;
    int f4 = t & 15;
    if (e < E) {
        int s = src[e], d = dst[e];
        float4 v = *(const float4*)(y + (size_t)s * 64 + f4 * 4);
        float* o = acc + (size_t)d * 64 + f4 * 4;
        asm volatile("red.global.add.v4.f32 [%0], {%1,%2,%3,%4};"
                     :: "l"(o), "f"(v.x), "f"(v.y), "f"(v.z), "f"(v.w)
                     : "memory");
    }
}

// ---------------------------------------------------------------------------
// pool: relu(rsqrt(deg[n])*acc[n][f] + b[f]) accumulated per sorted-batch run
// ---------------------------------------------------------------------------
#define POOL_CH 256
__global__ __launch_bounds__(256) void k_pool(const float* __restrict__ acc,
                                              const int* __restrict__ batch,
                                              const float* __restrict__ bias,
                                              const float* __restrict__ deg,
                                              int n, int colbase, int cntbase) {
    int f = threadIdx.x & 63;
    int grp = threadIdx.x >> 6;
    int n0 = blockIdx.x * POOL_CH;
    int nend = min(n0 + POOL_CH, n);
    float b = bias[f];
    float sum = 0.0f, cnt = 0.0f;
    int curg = -1;
    for (int nn = n0 + grp; nn < nend; nn += 4) {
        int g = batch[nn];
        if (g != curg) {
            if (curg >= 0) {
                atomicAdd(&g_pool[curg * 128 + colbase + f], sum);
                if (f == 0) atomicAdd(&g_cnt[cntbase + curg], cnt);
            }
            curg = g; sum = 0.0f; cnt = 0.0f;
        }
        float v = rsqrtf(deg[nn]) * acc[(size_t)nn * 64 + f] + b;
        sum += fmaxf(v, 0.0f);
        cnt += 1.0f;
    }
    if (curg >= 0) {
        atomicAdd(&g_pool[curg * 128 + colbase + f], sum);
        if (f == 0) atomicAdd(&g_cnt[cntbase + curg], cnt);
    }
}

__global__ void k_final(const float* __restrict__ linW, const float* __restrict__ linb,
                        float* __restrict__ out) {
    int t = threadIdx.x;
    int g = t >> 1, c = t & 1;
    float cp = fmaxf(g_cnt[g], 1.0f);
    float cr = fmaxf(g_cnt[NG + g], 1.0f);
    float s = linb[c];
#pragma unroll 8
    for (int j = 0; j < 64; j++)  s += (g_pool[g * 128 + j] / cp) * linW[j * 2 + c];
#pragma unroll 8
    for (int j = 64; j < 128; j++) s += (g_pool[g * 128 + j] / cr) * linW[j * 2 + c];
    out[g * 2 + c] = s;
}

// ---------------------------------------------------------------------------
extern "C" void kernel_launch(void* const* d_in, const int* in_sizes, int n_in,
                              void* d_out, int out_size) {
    const float* p_x   = (const float*)d_in[0];
    const int*   p_ei  = (const int*)d_in[1];
    const int*   p_bat = (const int*)d_in[2];
    const float* r_x   = (const float*)d_in[3];
    const int*   r_ei  = (const int*)d_in[4];
    const int*   r_bat = (const int*)d_in[5];
    const float* p_W   = (const float*)d_in[6];
    const float* p_b   = (const float*)d_in[7];
    const float* r_W   = (const float*)d_in[8];
    const float* r_b   = (const float*)d_in[9];
    const float* linW  = (const float*)d_in[10];
    const float* linb  = (const float*)d_in[11];
    float* out = (float*)d_out;

    int Np = in_sizes[2];
    int Kp = in_sizes[0] / Np;
    int Ep = in_sizes[1] / 2;
    int Nr = in_sizes[5];
    int Kr = in_sizes[3] / Nr;
    int Er = in_sizes[4] / 2;
    int KpPad = ((Kp + 63) / 64) * 64;
    int KrPad = ((Kr + 63) / 64) * 64;

    float *p_y, *r_y, *p_acc, *r_acc, *p_deg, *r_deg;
    __nv_bfloat16 *pWhi, *pWlo, *rWhi, *rWlo;
    cudaGetSymbolAddress((void**)&p_y, g_p_y);
    cudaGetSymbolAddress((void**)&r_y, g_r_y);
    cudaGetSymbolAddress((void**)&p_acc, g_p_acc);
    cudaGetSymbolAddress((void**)&r_acc, g_r_acc);
    cudaGetSymbolAddress((void**)&p_deg, g_p_deg);
    cudaGetSymbolAddress((void**)&r_deg, g_r_deg);
    cudaGetSymbolAddress((void**)&pWhi, g_pWhi);
    cudaGetSymbolAddress((void**)&pWlo, g_pWlo);
    cudaGetSymbolAddress((void**)&rWhi, g_rWhi);
    cudaGetSymbolAddress((void**)&rWlo, g_rWlo);

    int nmax = (Np > Nr ? Np : Nr);
    if (nmax < NG * 128) nmax = NG * 128;
    if (nmax < 64 * KpPad) nmax = 64 * KpPad;
    if (nmax < 64 * KrPad) nmax = 64 * KrPad;

    // launches 1-3
    k_init<<<(nmax + 255) / 256, 256>>>(Np, Nr, p_W, r_W, Kp, KpPad, Kr, KrPad);
    k_count<<<(Ep + 255) / 256, 256>>>(p_ei + Ep, Ep, p_deg);
    k_count<<<(Er + 255) / 256, 256>>>(r_ei + Er, Er, r_deg);

    // launch 4: p-branch GEMM (profiled slot)
    k_gemm_mma<<<(Np + 255) / 256, 256>>>(p_x, pWhi, pWlo, p_deg, p_y, p_acc, Np, Kp, KpPad);
    k_gemm_mma<<<(Nr + 255) / 256, 256>>>(r_x, rWhi, rWlo, r_deg, r_y, r_acc, Nr, Kr, KrPad);

    {
        long long tp = (long long)Ep * 16;
        k_scatter<<<(unsigned)((tp + 255) / 256), 256>>>(p_ei, p_ei + Ep, p_y, p_acc, Ep);
        long long tr = (long long)Er * 16;
        k_scatter<<<(unsigned)((tr + 255) / 256), 256>>>(r_ei, r_ei + Er, r_y, r_acc, Er);
    }

    k_pool<<<(Np + POOL_CH - 1) / POOL_CH, 256>>>(p_acc, p_bat, p_b, p_deg, Np, 0, 0);
    k_pool<<<(Nr + POOL_CH - 1) / POOL_CH, 256>>>(r_acc, r_bat, r_b, r_deg, Nr, 64, NG);

    k_final<<<1, 256>>>(linW, linb, out);
}

// round 7
// speedup vs baseline: 1.3230x; 1.0884x over previous
#include <cuda_runtime.h>
#include <cuda_bf16.h>
#include <cstdint>

#define NG 128
#define NPMAX 200000
#define NRMAX 400000

// ---- static scratch ----
__device__ __align__(16) float g_p_y  [NPMAX * 64];
__device__ __align__(16) float g_r_y  [NRMAX * 64];
__device__ __align__(16) float g_p_acc[NPMAX * 64];
__device__ __align__(16) float g_r_acc[NRMAX * 64];
__device__ float g_p_deg[NPMAX];
__device__ float g_r_deg[NRMAX];
__device__ float g_pool[NG * 128];
__device__ float g_cnt[2 * NG];
__device__ __align__(16) __nv_bfloat16 g_pWhi[64 * 1280];
__device__ __align__(16) __nv_bfloat16 g_pWlo[64 * 1280];
__device__ __align__(16) __nv_bfloat16 g_rWhi[64 * 128];
__device__ __align__(16) __nv_bfloat16 g_rWlo[64 * 128];

__device__ __forceinline__ uint32_t smem_u32(const void* p) {
    uint32_t a;
    asm("{ .reg .u64 t; cvta.to.shared.u64 t, %1; cvt.u32.u64 %0, t; }" : "=r"(a) : "l"(p));
    return a;
}

__device__ __forceinline__ void ldm_x4(uint32_t* r, uint32_t addr) {
    asm volatile("ldmatrix.sync.aligned.m8n8.x4.shared.b16 {%0,%1,%2,%3}, [%4];"
                 : "=r"(r[0]), "=r"(r[1]), "=r"(r[2]), "=r"(r[3]) : "r"(addr));
}

__device__ __forceinline__ void mma_bf16(float* d, const uint32_t* a, uint32_t b0, uint32_t b1) {
    asm volatile(
        "mma.sync.aligned.m16n8k16.row.col.f32.bf16.bf16.f32 "
        "{%0,%1,%2,%3}, {%4,%5,%6,%7}, {%8,%9}, {%0,%1,%2,%3};"
        : "+f"(d[0]), "+f"(d[1]), "+f"(d[2]), "+f"(d[3])
        : "r"(a[0]), "r"(a[1]), "r"(a[2]), "r"(a[3]), "r"(b0), "r"(b1));
}

// fp32 pair -> (hi bf16x2, lo bf16x2)
__device__ __forceinline__ void cvt_hilo(float x, float y, uint32_t& hi, uint32_t& lo) {
    __nv_bfloat162 h = __float22bfloat162_rn(make_float2(x, y));
    float hx = __low2float(h), hy = __high2float(h);
    __nv_bfloat162 l = __float22bfloat162_rn(make_float2(x - hx, y - hy));
    hi = *(uint32_t*)&h;
    lo = *(uint32_t*)&l;
}

// ---------------------------------------------------------------------------
// init (deg=1 self loop, pool/cnt=0) + W hi/lo split, fused
// ---------------------------------------------------------------------------
__global__ void k_init(int np, int nr,
                       const float* __restrict__ pW, const float* __restrict__ rW,
                       int Kp, int KpPad, int Kr, int KrPad) {
    int i = blockIdx.x * blockDim.x + threadIdx.x;
    if (i < np) g_p_deg[i] = 1.0f;
    if (i < nr) g_r_deg[i] = 1.0f;
    if (i < NG * 128) g_pool[i] = 0.0f;
    if (i < 2 * NG) g_cnt[i] = 0.0f;
    if (i < 64 * KpPad) {
        int n = i / KpPad, k = i % KpPad;
        float v = (k < Kp) ? pW[k * 64 + n] : 0.0f;
        __nv_bfloat16 h = __float2bfloat16_rn(v);
        g_pWhi[i] = h;
        g_pWlo[i] = __float2bfloat16_rn(v - __bfloat162float(h));
    }
    if (i < 64 * KrPad) {
        int n = i / KrPad, k = i % KrPad;
        float v = (k < Kr) ? rW[k * 64 + n] : 0.0f;
        __nv_bfloat16 h = __float2bfloat16_rn(v);
        g_rWhi[i] = h;
        g_rWlo[i] = __float2bfloat16_rn(v - __bfloat162float(h));
    }
}

__global__ void k_count(const int* __restrict__ dst, int E, float* __restrict__ deg) {
    int e = blockIdx.x * blockDim.x + threadIdx.x;
    if (e < E) atomicAdd(&deg[dst[e]], 1.0f);
}

// ---------------------------------------------------------------------------
// HMMA GEMM, bf16x3. CTA tile 256x64, 8 warps, warp tile m32 x n64.
// A fragments direct global->regs; B staged in smem, ldmatrix.x4.
// __launch_bounds__(256,2): cap 128 regs -> 2 CTAs/SM for latency hiding.
// Epilogue: y = xw * rsqrt(deg); writes Y and ACC (self-loop term).
// ---------------------------------------------------------------------------
#define KC 64
#define BPAD 8
#define BSTR (KC + BPAD)   // 72 bf16 per B row

__global__ __launch_bounds__(256, 2) void k_gemm_mma(
    const float* __restrict__ X,
    const __nv_bfloat16* __restrict__ Whi, const __nv_bfloat16* __restrict__ Wlo,
    const float* __restrict__ deg,
    float* __restrict__ Y, float* __restrict__ ACC,
    int M, int K, int Kpad)
{
    __shared__ __align__(16) __nv_bfloat16 sBhi[64 * BSTR];
    __shared__ __align__(16) __nv_bfloat16 sBlo[64 * BSTR];
    uint32_t uBhi = smem_u32(sBhi), uBlo = smem_u32(sBlo);

    int tid = threadIdx.x;
    int w = tid >> 5, lane = tid & 31;
    int g = lane >> 2, tg = lane & 3;

    // B loader: t<128 -> hi, t>=128 -> lo; n=(t&127)/2, k-half
    int bt = tid & 127;
    int bn = bt >> 1;
    int bkh = (bt & 1) * 32;
    const __nv_bfloat16* bsrc = ((tid < 128) ? Whi : Wlo) + (size_t)bn * Kpad + bkh;
    __nv_bfloat16* bdst = ((tid < 128) ? sBhi : sBlo) + bn * BSTR + bkh;

    // B-frag ldmatrix.x4 per-lane offset
    int bTile = lane >> 3;
    uint32_t bfoff = (uint32_t)(((bTile >> 1) * 8 + (lane & 7)) * BSTR + (bTile & 1) * 8) * 2;

    // A rows for this warp: base row, slabs mt at +0/+16, pairs at +0/+8
    int rowBase = blockIdx.x * 256 + w * 32;
    int rA = rowBase + g;           // slab0 row0
    const float* xbase = X + (size_t)rA * K;
    // guard rows against M
    bool ok00 = (rA)      < M, ok01 = (rA + 8)  < M;
    bool ok10 = (rA + 16) < M, ok11 = (rA + 24) < M;
    size_t s8  = (size_t)8 * K, s16 = (size_t)16 * K, s24 = (size_t)24 * K;

    float d[2][8][4];
#pragma unroll
    for (int mt = 0; mt < 2; mt++)
#pragma unroll
        for (int nt = 0; nt < 8; nt++)
#pragma unroll
            for (int j = 0; j < 4; j++) d[mt][nt][j] = 0.0f;

    const float2 z2 = make_float2(0.f, 0.f);
    int nchunks = Kpad / KC;

    for (int ch = 0; ch < nchunks; ch++) {
        int k0 = ch * KC;
        if (ch > 0) __syncthreads();
        // ---- stage B chunk ----
        {
            const uint4* s = (const uint4*)(bsrc + k0);
            uint4* dq = (uint4*)bdst;
#pragma unroll
            for (int q = 0; q < 4; q++) dq[q] = s[q];
        }
        __syncthreads();

#pragma unroll
        for (int ks = 0; ks < KC / 16; ks++) {
            int kk = k0 + ks * 16 + tg * 2;
            bool kOK0 = (kk + 2) <= K;
            bool kOK1 = (kk + 10) <= K;

            // ---- A fragments direct from global ----
            uint32_t ah[2][4], al[2][4];
            {
                float2 f;
                f = (ok00 && kOK0) ? *(const float2*)(xbase + kk) : z2;
                cvt_hilo(f.x, f.y, ah[0][0], al[0][0]);
                f = (ok01 && kOK0) ? *(const float2*)(xbase + s8 + kk) : z2;
                cvt_hilo(f.x, f.y, ah[0][1], al[0][1]);
                f = (ok00 && kOK1) ? *(const float2*)(xbase + kk + 8) : z2;
                cvt_hilo(f.x, f.y, ah[0][2], al[0][2]);
                f = (ok01 && kOK1) ? *(const float2*)(xbase + s8 + kk + 8) : z2;
                cvt_hilo(f.x, f.y, ah[0][3], al[0][3]);
                f = (ok10 && kOK0) ? *(const float2*)(xbase + s16 + kk) : z2;
                cvt_hilo(f.x, f.y, ah[1][0], al[1][0]);
                f = (ok11 && kOK0) ? *(const float2*)(xbase + s24 + kk) : z2;
                cvt_hilo(f.x, f.y, ah[1][1], al[1][1]);
                f = (ok10 && kOK1) ? *(const float2*)(xbase + s16 + kk + 8) : z2;
                cvt_hilo(f.x, f.y, ah[1][2], al[1][2]);
                f = (ok11 && kOK1) ? *(const float2*)(xbase + s24 + kk + 8) : z2;
                cvt_hilo(f.x, f.y, ah[1][3], al[1][3]);
            }

            // ---- B fragments + MMA ----
#pragma unroll
            for (int np = 0; np < 4; np++) {
                uint32_t boffc = bfoff + (uint32_t)(np * 16 * BSTR + ks * 16) * 2;
                uint32_t bh[4], bl[4];
                ldm_x4(bh, uBhi + boffc);
                ldm_x4(bl, uBlo + boffc);
#pragma unroll
                for (int mt = 0; mt < 2; mt++) {
                    mma_bf16(d[mt][np * 2],     ah[mt], bh[0], bh[1]);
                    mma_bf16(d[mt][np * 2],     al[mt], bh[0], bh[1]);
                    mma_bf16(d[mt][np * 2],     ah[mt], bl[0], bl[1]);
                    mma_bf16(d[mt][np * 2 + 1], ah[mt], bh[2], bh[3]);
                    mma_bf16(d[mt][np * 2 + 1], al[mt], bh[2], bh[3]);
                    mma_bf16(d[mt][np * 2 + 1], ah[mt], bl[2], bl[3]);
                }
            }
        }
    }

    // ---- epilogue: y = xw * rsqrt(deg); write Y and ACC ----
#pragma unroll
    for (int mt = 0; mt < 2; mt++) {
#pragma unroll
        for (int rs = 0; rs < 2; rs++) {
            int row = rowBase + mt * 16 + g + rs * 8;
            if (row < M) {
                float dv = rsqrtf(deg[row]);
                float* yp = Y + (size_t)row * 64;
                float* ac = ACC + (size_t)row * 64;
#pragma unroll
                for (int nt = 0; nt < 8; nt++) {
                    int col = nt * 8 + 2 * tg;
                    float2 v = make_float2(d[mt][nt][2 * rs] * dv, d[mt][nt][2 * rs + 1] * dv);
                    *(float2*)(yp + col) = v;
                    *(float2*)(ac + col) = v;
                }
            }
        }
    }
}

// ---------------------------------------------------------------------------
// edge scatter: acc[dst] += y[src]; 16 thr/edge, v4 red
// ---------------------------------------------------------------------------
__global__ void k_scatter(const int* __restrict__ src, const int* __restrict__ dst,
                          const float* __restrict__ y, float* __restrict__ acc, int E) {
    int t = blockIdx.x * blockDim.x + threadIdx.x;
    int e = t >> 4;
    int f4 = t & 15;
    if (e < E) {
        int s = src[e], d = dst[e];
        float4 v = *(const float4*)(y + (size_t)s * 64 + f4 * 4);
        float* o = acc + (size_t)d * 64 + f4 * 4;
        asm volatile("red.global.add.v4.f32 [%0], {%1,%2,%3,%4};"
                     :: "l"(o), "f"(v.x), "f"(v.y), "f"(v.z), "f"(v.w)
                     : "memory");
    }
}

// ---------------------------------------------------------------------------
// pool: relu(rsqrt(deg[n])*acc[n][f] + b[f]) accumulated per sorted-batch run
// ---------------------------------------------------------------------------
#define POOL_CH 256
__global__ __launch_bounds__(256) void k_pool(const float* __restrict__ acc,
                                              const int* __restrict__ batch,
                                              const float* __restrict__ bias,
                                              const float* __restrict__ deg,
                                              int n, int colbase, int cntbase) {
    int f = threadIdx.x & 63;
    int grp = threadIdx.x >> 6;
    int n0 = blockIdx.x * POOL_CH;
    int nend = min(n0 + POOL_CH, n);
    float b = bias[f];
    float sum = 0.0f, cnt = 0.0f;
    int curg = -1;
    for (int nn = n0 + grp; nn < nend; nn += 4) {
        int g = batch[nn];
        if (g != curg) {
            if (curg >= 0) {
                atomicAdd(&g_pool[curg * 128 + colbase + f], sum);
                if (f == 0) atomicAdd(&g_cnt[cntbase + curg], cnt);
            }
            curg = g; sum = 0.0f; cnt = 0.0f;
        }
        float v = rsqrtf(deg[nn]) * acc[(size_t)nn * 64 + f] + b;
        sum += fmaxf(v, 0.0f);
        cnt += 1.0f;
    }
    if (curg >= 0) {
        atomicAdd(&g_pool[curg * 128 + colbase + f], sum);
        if (f == 0) atomicAdd(&g_cnt[cntbase + curg], cnt);
    }
}

__global__ void k_final(const float* __restrict__ linW, const float* __restrict__ linb,
                        float* __restrict__ out) {
    int t = threadIdx.x;
    int g = t >> 1, c = t & 1;
    float cp = fmaxf(g_cnt[g], 1.0f);
    float cr = fmaxf(g_cnt[NG + g], 1.0f);
    float s = linb[c];
#pragma unroll 8
    for (int j = 0; j < 64; j++)  s += (g_pool[g * 128 + j] / cp) * linW[j * 2 + c];
#pragma unroll 8
    for (int j = 64; j < 128; j++) s += (g_pool[g * 128 + j] / cr) * linW[j * 2 + c];
    out[g * 2 + c] = s;
}

// ---------------------------------------------------------------------------
extern "C" void kernel_launch(void* const* d_in, const int* in_sizes, int n_in,
                              void* d_out, int out_size) {
    const float* p_x   = (const float*)d_in[0];
    const int*   p_ei  = (const int*)d_in[1];
    const int*   p_bat = (const int*)d_in[2];
    const float* r_x   = (const float*)d_in[3];
    const int*   r_ei  = (const int*)d_in[4];
    const int*   r_bat = (const int*)d_in[5];
    const float* p_W   = (const float*)d_in[6];
    const float* p_b   = (const float*)d_in[7];
    const float* r_W   = (const float*)d_in[8];
    const float* r_b   = (const float*)d_in[9];
    const float* linW  = (const float*)d_in[10];
    const float* linb  = (const float*)d_in[11];
    float* out = (float*)d_out;

    int Np = in_sizes[2];
    int Kp = in_sizes[0] / Np;
    int Ep = in_sizes[1] / 2;
    int Nr = in_sizes[5];
    int Kr = in_sizes[3] / Nr;
    int Er = in_sizes[4] / 2;
    int KpPad = ((Kp + 63) / 64) * 64;
    int KrPad = ((Kr + 63) / 64) * 64;

    float *p_y, *r_y, *p_acc, *r_acc, *p_deg, *r_deg;
    __nv_bfloat16 *pWhi, *pWlo, *rWhi, *rWlo;
    cudaGetSymbolAddress((void**)&p_y, g_p_y);
    cudaGetSymbolAddress((void**)&r_y, g_r_y);
    cudaGetSymbolAddress((void**)&p_acc, g_p_acc);
    cudaGetSymbolAddress((void**)&r_acc, g_r_acc);
    cudaGetSymbolAddress((void**)&p_deg, g_p_deg);
    cudaGetSymbolAddress((void**)&r_deg, g_r_deg);
    cudaGetSymbolAddress((void**)&pWhi, g_pWhi);
    cudaGetSymbolAddress((void**)&pWlo, g_pWlo);
    cudaGetSymbolAddress((void**)&rWhi, g_rWhi);
    cudaGetSymbolAddress((void**)&rWlo, g_rWlo);

    int nmax = (Np > Nr ? Np : Nr);
    if (nmax < NG * 128) nmax = NG * 128;
    if (nmax < 64 * KpPad) nmax = 64 * KpPad;
    if (nmax < 64 * KrPad) nmax = 64 * KrPad;

    // launches 1-3
    k_init<<<(nmax + 255) / 256, 256>>>(Np, Nr, p_W, r_W, Kp, KpPad, Kr, KrPad);
    k_count<<<(Ep + 255) / 256, 256>>>(p_ei + Ep, Ep, p_deg);
    k_count<<<(Er + 255) / 256, 256>>>(r_ei + Er, Er, r_deg);

    // launch 4: p-branch GEMM (profiled slot)
    k_gemm_mma<<<(Np + 255) / 256, 256>>>(p_x, pWhi, pWlo, p_deg, p_y, p_acc, Np, Kp, KpPad);
    k_gemm_mma<<<(Nr + 255) / 256, 256>>>(r_x, rWhi, rWlo, r_deg, r_y, r_acc, Nr, Kr, KrPad);

    {
        long long tp = (long long)Ep * 16;
        k_scatter<<<(unsigned)((tp + 255) / 256), 256>>>(p_ei, p_ei + Ep, p_y, p_acc, Ep);
        long long tr = (long long)Er * 16;
        k_scatter<<<(unsigned)((tr + 255) / 256), 256>>>(r_ei, r_ei + Er, r_y, r_acc, Er);
    }

    k_pool<<<(Np + POOL_CH - 1) / POOL_CH, 256>>>(p_acc, p_bat, p_b, p_deg, Np, 0, 0);
    k_pool<<<(Nr + POOL_CH - 1) / POOL_CH, 256>>>(r_acc, r_bat, r_b, r_deg, Nr, 64, NG);

    k_final<<<1, 256>>>(linW, linb, out);
}

// round 8
// speedup vs baseline: 1.4255x; 1.0774x over previous
#include <cuda_runtime.h>
#include <cuda_bf16.h>
#include <cstdint>

#define NG 128
#define NPMAX 200000
#define NRMAX 400000
#define EMAX 2000000

// ---- static scratch ----
__device__ __align__(16) float g_p_y  [NPMAX * 64];
__device__ __align__(16) float g_r_y  [NRMAX * 64];
__device__ __align__(16) float g_p_acc[NPMAX * 64];
__device__ __align__(16) float g_r_acc[NRMAX * 64];
__device__ int   g_p_cnt[NPMAX];
__device__ int   g_r_cnt[NRMAX];
__device__ int   g_p_off[NPMAX];
__device__ int   g_r_off[NRMAX];
__device__ int   g_p_pos[NPMAX];
__device__ int   g_r_pos[NRMAX];
__device__ int   g_p_srcs[EMAX];
__device__ int   g_r_srcs[EMAX];
__device__ int   g_bs[128];
__device__ float g_pool[NG * 128];
__device__ float g_cnt[2 * NG];
__device__ __align__(16) __nv_bfloat16 g_pWhi[64 * 1280];
__device__ __align__(16) __nv_bfloat16 g_pWlo[64 * 1280];
__device__ __align__(16) __nv_bfloat16 g_rWhi[64 * 128];
__device__ __align__(16) __nv_bfloat16 g_rWlo[64 * 128];

__device__ __forceinline__ uint32_t smem_u32(const void* p) {
    uint32_t a;
    asm("{ .reg .u64 t; cvta.to.shared.u64 t, %1; cvt.u32.u64 %0, t; }" : "=r"(a) : "l"(p));
    return a;
}

__device__ __forceinline__ void ldm_x4(uint32_t* r, uint32_t addr) {
    asm volatile("ldmatrix.sync.aligned.m8n8.x4.shared.b16 {%0,%1,%2,%3}, [%4];"
                 : "=r"(r[0]), "=r"(r[1]), "=r"(r[2]), "=r"(r[3]) : "r"(addr));
}

__device__ __forceinline__ void mma_bf16(float* d, const uint32_t* a, uint32_t b0, uint32_t b1) {
    asm volatile(
        "mma.sync.aligned.m16n8k16.row.col.f32.bf16.bf16.f32 "
        "{%0,%1,%2,%3}, {%4,%5,%6,%7}, {%8,%9}, {%0,%1,%2,%3};"
        : "+f"(d[0]), "+f"(d[1]), "+f"(d[2]), "+f"(d[3])
        : "r"(a[0]), "r"(a[1]), "r"(a[2]), "r"(a[3]), "r"(b0), "r"(b1));
}

__device__ __forceinline__ void cvt_hilo(float x, float y, uint32_t& hi, uint32_t& lo) {
    __nv_bfloat162 h = __float22bfloat162_rn(make_float2(x, y));
    float hx = __low2float(h), hy = __high2float(h);
    __nv_bfloat162 l = __float22bfloat162_rn(make_float2(x - hx, y - hy));
    hi = *(uint32_t*)&h;
    lo = *(uint32_t*)&l;
}

// ---------------------------------------------------------------------------
// init: cnt=0, pool/cnt=0, W hi/lo split
// ---------------------------------------------------------------------------
__global__ void k_init(int np, int nr,
                       const float* __restrict__ pW, const float* __restrict__ rW,
                       int Kp, int KpPad, int Kr, int KrPad) {
    int i = blockIdx.x * blockDim.x + threadIdx.x;
    if (i < np) g_p_cnt[i] = 0;
    if (i < nr) g_r_cnt[i] = 0;
    if (i < NG * 128) g_pool[i] = 0.0f;
    if (i < 2 * NG) g_cnt[i] = 0.0f;
    if (i < 64 * KpPad) {
        int n = i / KpPad, k = i % KpPad;
        float v = (k < Kp) ? pW[k * 64 + n] : 0.0f;
        __nv_bfloat16 h = __float2bfloat16_rn(v);
        g_pWhi[i] = h;
        g_pWlo[i] = __float2bfloat16_rn(v - __bfloat162float(h));
    }
    if (i < 64 * KrPad) {
        int n = i / KrPad, k = i % KrPad;
        float v = (k < Kr) ? rW[k * 64 + n] : 0.0f;
        __nv_bfloat16 h = __float2bfloat16_rn(v);
        g_rWhi[i] = h;
        g_rWlo[i] = __float2bfloat16_rn(v - __bfloat162float(h));
    }
}

__global__ void k_count(const int* __restrict__ dst, int E, int* __restrict__ cnt) {
    int e = blockIdx.x * blockDim.x + threadIdx.x;
    if (e < E) atomicAdd(&cnt[dst[e]], 1);
}

// ---------------------------------------------------------------------------
// exclusive scan of cnt[n] -> off[n] (3 kernels, 4096 elems/block)
// ---------------------------------------------------------------------------
__global__ __launch_bounds__(256) void k_s1(const int* __restrict__ cnt, int n, int* __restrict__ bs) {
    __shared__ int sm[256];
    int base = blockIdx.x * 4096, t = threadIdx.x;
    int sum = 0;
#pragma unroll
    for (int j = 0; j < 16; j++) {
        int i = base + t + 256 * j;
        if (i < n) sum += cnt[i];
    }
    sm[t] = sum; __syncthreads();
#pragma unroll
    for (int s = 128; s > 0; s >>= 1) {
        if (t < s) sm[t] += sm[t + s];
        __syncthreads();
    }
    if (t == 0) bs[blockIdx.x] = sm[0];
}

__global__ __launch_bounds__(128) void k_s2(int* __restrict__ bs, int nb) {
    __shared__ int sm[128];
    int t = threadIdx.x;
    int orig = (t < nb) ? bs[t] : 0;
    sm[t] = orig; __syncthreads();
#pragma unroll
    for (int o = 1; o < 128; o <<= 1) {
        int v = (t >= o) ? sm[t - o] : 0;
        __syncthreads();
        sm[t] += v;
        __syncthreads();
    }
    if (t < nb) bs[t] = sm[t] - orig;   // exclusive
}

__global__ __launch_bounds__(256) void k_s3(const int* __restrict__ cnt, int n,
                                            const int* __restrict__ bs,
                                            int* __restrict__ off, int* __restrict__ pos) {
    __shared__ int stage[4096];
    __shared__ int tsum[256];
    int base = blockIdx.x * 4096, t = threadIdx.x;
#pragma unroll
    for (int j = 0; j < 16; j++) {
        int i = base + t + 256 * j;
        stage[t + 256 * j] = (i < n) ? cnt[i] : 0;
    }
    __syncthreads();
    int loc[16];
    int s = 0;
#pragma unroll
    for (int j = 0; j < 16; j++) { loc[j] = s; s += stage[t * 16 + j]; }
    int orig = s;
    tsum[t] = s; __syncthreads();
#pragma unroll
    for (int o = 1; o < 256; o <<= 1) {
        int v = (t >= o) ? tsum[t - o] : 0;
        __syncthreads();
        tsum[t] += v;
        __syncthreads();
    }
    int toff = tsum[t] - orig + bs[blockIdx.x];
#pragma unroll
    for (int j = 0; j < 16; j++) {
        int i = base + t * 16 + j;
        if (i < n) { int o2 = toff + loc[j]; off[i] = o2; pos[i] = o2; }
    }
}

// fill CSR: srcs grouped by dst
__global__ void k_fill(const int* __restrict__ src, const int* __restrict__ dst,
                       int* __restrict__ pos, int* __restrict__ srcs, int E) {
    int e = blockIdx.x * blockDim.x + threadIdx.x;
    if (e < E) {
        int p = atomicAdd(&pos[dst[e]], 1);
        srcs[p] = src[e];
    }
}

// ---------------------------------------------------------------------------
// HMMA GEMM, bf16x3. CTA 256x64, 8 warps, warp m32 x n64.
// A direct global->regs; B staged in smem, ldmatrix.x4. 2 CTAs/SM.
// Epilogue: Y = xw * rsqrt(cnt+1)   (no ACC write; gather handles aggregation)
// ---------------------------------------------------------------------------
#define KC 64
#define BPAD 8
#define BSTR (KC + BPAD)

__global__ __launch_bounds__(256, 2) void k_gemm_mma(
    const float* __restrict__ X,
    const __nv_bfloat16* __restrict__ Whi, const __nv_bfloat16* __restrict__ Wlo,
    const int* __restrict__ cnt,
    float* __restrict__ Y,
    int M, int K, int Kpad)
{
    __shared__ __align__(16) __nv_bfloat16 sBhi[64 * BSTR];
    __shared__ __align__(16) __nv_bfloat16 sBlo[64 * BSTR];
    uint32_t uBhi = smem_u32(sBhi), uBlo = smem_u32(sBlo);

    int tid = threadIdx.x;
    int w = tid >> 5, lane = tid & 31;
    int g = lane >> 2, tg = lane & 3;

    int bt = tid & 127;
    int bn = bt >> 1;
    int bkh = (bt & 1) * 32;
    const __nv_bfloat16* bsrc = ((tid < 128) ? Whi : Wlo) + (size_t)bn * Kpad + bkh;
    __nv_bfloat16* bdst = ((tid < 128) ? sBhi : sBlo) + bn * BSTR + bkh;

    int bTile = lane >> 3;
    uint32_t bfoff = (uint32_t)(((bTile >> 1) * 8 + (lane & 7)) * BSTR + (bTile & 1) * 8) * 2;

    int rowBase = blockIdx.x * 256 + w * 32;
    int rA = rowBase + g;
    const float* xbase = X + (size_t)rA * K;
    bool ok00 = (rA)      < M, ok01 = (rA + 8)  < M;
    bool ok10 = (rA + 16) < M, ok11 = (rA + 24) < M;
    size_t s8 = (size_t)8 * K, s16 = (size_t)16 * K, s24 = (size_t)24 * K;

    float d[2][8][4];
#pragma unroll
    for (int mt = 0; mt < 2; mt++)
#pragma unroll
        for (int nt = 0; nt < 8; nt++)
#pragma unroll
            for (int j = 0; j < 4; j++) d[mt][nt][j] = 0.0f;

    const float2 z2 = make_float2(0.f, 0.f);
    int nchunks = Kpad / KC;

    for (int ch = 0; ch < nchunks; ch++) {
        int k0 = ch * KC;
        if (ch > 0) __syncthreads();
        {
            const uint4* s = (const uint4*)(bsrc + k0);
            uint4* dq = (uint4*)bdst;
#pragma unroll
            for (int q = 0; q < 4; q++) dq[q] = s[q];
        }
        __syncthreads();

#pragma unroll
        for (int ks = 0; ks < KC / 16; ks++) {
            int kk = k0 + ks * 16 + tg * 2;
            bool kOK0 = (kk + 2) <= K;
            bool kOK1 = (kk + 10) <= K;

            uint32_t ah[2][4], al[2][4];
            {
                float2 f;
                f = (ok00 && kOK0) ? *(const float2*)(xbase + kk) : z2;
                cvt_hilo(f.x, f.y, ah[0][0], al[0][0]);
                f = (ok01 && kOK0) ? *(const float2*)(xbase + s8 + kk) : z2;
                cvt_hilo(f.x, f.y, ah[0][1], al[0][1]);
                f = (ok00 && kOK1) ? *(const float2*)(xbase + kk + 8) : z2;
                cvt_hilo(f.x, f.y, ah[0][2], al[0][2]);
                f = (ok01 && kOK1) ? *(const float2*)(xbase + s8 + kk + 8) : z2;
                cvt_hilo(f.x, f.y, ah[0][3], al[0][3]);
                f = (ok10 && kOK0) ? *(const float2*)(xbase + s16 + kk) : z2;
                cvt_hilo(f.x, f.y, ah[1][0], al[1][0]);
                f = (ok11 && kOK0) ? *(const float2*)(xbase + s24 + kk) : z2;
                cvt_hilo(f.x, f.y, ah[1][1], al[1][1]);
                f = (ok10 && kOK1) ? *(const float2*)(xbase + s16 + kk + 8) : z2;
                cvt_hilo(f.x, f.y, ah[1][2], al[1][2]);
                f = (ok11 && kOK1) ? *(const float2*)(xbase + s24 + kk + 8) : z2;
                cvt_hilo(f.x, f.y, ah[1][3], al[1][3]);
            }

#pragma unroll
            for (int np = 0; np < 4; np++) {
                uint32_t boffc = bfoff + (uint32_t)(np * 16 * BSTR + ks * 16) * 2;
                uint32_t bh[4], bl[4];
                ldm_x4(bh, uBhi + boffc);
                ldm_x4(bl, uBlo + boffc);
#pragma unroll
                for (int mt = 0; mt < 2; mt++) {
                    mma_bf16(d[mt][np * 2],     ah[mt], bh[0], bh[1]);
                    mma_bf16(d[mt][np * 2],     al[mt], bh[0], bh[1]);
                    mma_bf16(d[mt][np * 2],     ah[mt], bl[0], bl[1]);
                    mma_bf16(d[mt][np * 2 + 1], ah[mt], bh[2], bh[3]);
                    mma_bf16(d[mt][np * 2 + 1], al[mt], bh[2], bh[3]);
                    mma_bf16(d[mt][np * 2 + 1], ah[mt], bl[2], bl[3]);
                }
            }
        }
    }

    // epilogue: Y = xw * rsqrt(cnt+1)
#pragma unroll
    for (int mt = 0; mt < 2; mt++) {
#pragma unroll
        for (int rs = 0; rs < 2; rs++) {
            int row = rowBase + mt * 16 + g + rs * 8;
            if (row < M) {
                float dv = rsqrtf((float)(cnt[row] + 1));
                float* yp = Y + (size_t)row * 64;
#pragma unroll
                for (int nt = 0; nt < 8; nt++) {
                    int col = nt * 8 + 2 * tg;
                    *(float2*)(yp + col) = make_float2(d[mt][nt][2 * rs] * dv,
                                                       d[mt][nt][2 * rs + 1] * dv);
                }
            }
        }
    }
}

// ---------------------------------------------------------------------------
// gather: acc[node] = y[node] + sum_{s in in(node)} y[s]; warp per node
// ---------------------------------------------------------------------------
__global__ __launch_bounds__(256) void k_gather(const float* __restrict__ y,
                                                const int* __restrict__ off,
                                                const int* __restrict__ cnt,
                                                const int* __restrict__ srcs,
                                                float* __restrict__ acc, int n) {
    int node = blockIdx.x * 8 + (threadIdx.x >> 5);
    int lane = threadIdx.x & 31;
    if (node >= n) return;
    int c = lane * 2;
    float2 a = *(const float2*)(y + (size_t)node * 64 + c);
    int j = off[node];
    int e = j + cnt[node];
    // 2-deep src prefetch to break the srcs->y dependency chain
    int s0 = (j < e) ? srcs[j] : 0;
    int s1 = (j + 1 < e) ? srcs[j + 1] : 0;
    for (; j + 1 < e; j += 2) {
        float2 v0 = *(const float2*)(y + (size_t)s0 * 64 + c);
        float2 v1 = *(const float2*)(y + (size_t)s1 * 64 + c);
        s0 = (j + 2 < e) ? srcs[j + 2] : 0;
        s1 = (j + 3 < e) ? srcs[j + 3] : 0;
        a.x += v0.x + v1.x;
        a.y += v0.y + v1.y;
    }
    if (j < e) {
        float2 v = *(const float2*)(y + (size_t)s0 * 64 + c);
        a.x += v.x; a.y += v.y;
    }
    *(float2*)(acc + (size_t)node * 64 + c) = a;
}

// ---------------------------------------------------------------------------
// pool: relu(rsqrt(cnt+1)*acc + b) accumulated per sorted-batch run
// ---------------------------------------------------------------------------
#define POOL_CH 256
__global__ __launch_bounds__(256) void k_pool(const float* __restrict__ acc,
                                              const int* __restrict__ batch,
                                              const float* __restrict__ bias,
                                              const int* __restrict__ cntArr,
                                              int n, int colbase, int cntbase) {
    int f = threadIdx.x & 63;
    int grp = threadIdx.x >> 6;
    int n0 = blockIdx.x * POOL_CH;
    int nend = min(n0 + POOL_CH, n);
    float b = bias[f];
    float sum = 0.0f, cnt = 0.0f;
    int curg = -1;
    for (int nn = n0 + grp; nn < nend; nn += 4) {
        int g = batch[nn];
        if (g != curg) {
            if (curg >= 0) {
                atomicAdd(&g_pool[curg * 128 + colbase + f], sum);
                if (f == 0) atomicAdd(&g_cnt[cntbase + curg], cnt);
            }
            curg = g; sum = 0.0f; cnt = 0.0f;
        }
        float v = rsqrtf((float)(cntArr[nn] + 1)) * acc[(size_t)nn * 64 + f] + b;
        sum += fmaxf(v, 0.0f);
        cnt += 1.0f;
    }
    if (curg >= 0) {
        atomicAdd(&g_pool[curg * 128 + colbase + f], sum);
        if (f == 0) atomicAdd(&g_cnt[cntbase + curg], cnt);
    }
}

__global__ void k_final(const float* __restrict__ linW, const float* __restrict__ linb,
                        float* __restrict__ out) {
    int t = threadIdx.x;
    int g = t >> 1, c = t & 1;
    float cp = fmaxf(g_cnt[g], 1.0f);
    float cr = fmaxf(g_cnt[NG + g], 1.0f);
    float s = linb[c];
#pragma unroll 8
    for (int j = 0; j < 64; j++)  s += (g_pool[g * 128 + j] / cp) * linW[j * 2 + c];
#pragma unroll 8
    for (int j = 64; j < 128; j++) s += (g_pool[g * 128 + j] / cr) * linW[j * 2 + c];
    out[g * 2 + c] = s;
}

// ---------------------------------------------------------------------------
extern "C" void kernel_launch(void* const* d_in, const int* in_sizes, int n_in,
                              void* d_out, int out_size) {
    const float* p_x   = (const float*)d_in[0];
    const int*   p_ei  = (const int*)d_in[1];
    const int*   p_bat = (const int*)d_in[2];
    const float* r_x   = (const float*)d_in[3];
    const int*   r_ei  = (const int*)d_in[4];
    const int*   r_bat = (const int*)d_in[5];
    const float* p_W   = (const float*)d_in[6];
    const float* p_b   = (const float*)d_in[7];
    const float* r_W   = (const float*)d_in[8];
    const float* r_b   = (const float*)d_in[9];
    const float* linW  = (const float*)d_in[10];
    const float* linb  = (const float*)d_in[11];
    float* out = (float*)d_out;

    int Np = in_sizes[2];
    int Kp = in_sizes[0] / Np;
    int Ep = in_sizes[1] / 2;
    int Nr = in_sizes[5];
    int Kr = in_sizes[3] / Nr;
    int Er = in_sizes[4] / 2;
    int KpPad = ((Kp + 63) / 64) * 64;
    int KrPad = ((Kr + 63) / 64) * 64;

    float *p_y, *r_y, *p_acc, *r_acc;
    int *p_cnt, *r_cnt, *p_off, *r_off, *p_pos, *r_pos, *p_srcs, *r_srcs, *bs;
    __nv_bfloat16 *pWhi, *pWlo, *rWhi, *rWlo;
    cudaGetSymbolAddress((void**)&p_y, g_p_y);
    cudaGetSymbolAddress((void**)&r_y, g_r_y);
    cudaGetSymbolAddress((void**)&p_acc, g_p_acc);
    cudaGetSymbolAddress((void**)&r_acc, g_r_acc);
    cudaGetSymbolAddress((void**)&p_cnt, g_p_cnt);
    cudaGetSymbolAddress((void**)&r_cnt, g_r_cnt);
    cudaGetSymbolAddress((void**)&p_off, g_p_off);
    cudaGetSymbolAddress((void**)&r_off, g_r_off);
    cudaGetSymbolAddress((void**)&p_pos, g_p_pos);
    cudaGetSymbolAddress((void**)&r_pos, g_r_pos);
    cudaGetSymbolAddress((void**)&p_srcs, g_p_srcs);
    cudaGetSymbolAddress((void**)&r_srcs, g_r_srcs);
    cudaGetSymbolAddress((void**)&bs, g_bs);
    cudaGetSymbolAddress((void**)&pWhi, g_pWhi);
    cudaGetSymbolAddress((void**)&pWlo, g_pWlo);
    cudaGetSymbolAddress((void**)&rWhi, g_rWhi);
    cudaGetSymbolAddress((void**)&rWlo, g_rWlo);

    int nmax = (Np > Nr ? Np : Nr);
    if (nmax < NG * 128) nmax = NG * 128;
    if (nmax < 64 * KpPad) nmax = 64 * KpPad;
    if (nmax < 64 * KrPad) nmax = 64 * KrPad;

    int nbP = (Np + 4095) / 4096;
    int nbR = (Nr + 4095) / 4096;

    // launches 1-3
    k_init<<<(nmax + 255) / 256, 256>>>(Np, Nr, p_W, r_W, Kp, KpPad, Kr, KrPad);
    k_count<<<(Ep + 255) / 256, 256>>>(p_ei + Ep, Ep, p_cnt);
    k_count<<<(Er + 255) / 256, 256>>>(r_ei + Er, Er, r_cnt);

    // launch 4: p-branch GEMM (profiled slot)
    k_gemm_mma<<<(Np + 255) / 256, 256>>>(p_x, pWhi, pWlo, p_cnt, p_y, Np, Kp, KpPad);
    k_gemm_mma<<<(Nr + 255) / 256, 256>>>(r_x, rWhi, rWlo, r_cnt, r_y, Nr, Kr, KrPad);

    // CSR build p
    k_s1<<<nbP, 256>>>(p_cnt, Np, bs);
    k_s2<<<1, 128>>>(bs, nbP);
    k_s3<<<nbP, 256>>>(p_cnt, Np, bs, p_off, p_pos);
    k_fill<<<(Ep + 255) / 256, 256>>>(p_ei, p_ei + Ep, p_pos, p_srcs, Ep);
    // CSR build r
    k_s1<<<nbR, 256>>>(r_cnt, Nr, bs);
    k_s2<<<1, 128>>>(bs, nbR);
    k_s3<<<nbR, 256>>>(r_cnt, Nr, bs, r_off, r_pos);
    k_fill<<<(Er + 255) / 256, 256>>>(r_ei, r_ei + Er, r_pos, r_srcs, Er);

    // gather
    k_gather<<<(Np + 7) / 8, 256>>>(p_y, p_off, p_cnt, p_srcs, p_acc, Np);
    k_gather<<<(Nr + 7) / 8, 256>>>(r_y, r_off, r_cnt, r_srcs, r_acc, Nr);

    // pool + head
    k_pool<<<(Np + POOL_CH - 1) / POOL_CH, 256>>>(p_acc, p_bat, p_b, p_cnt, Np, 0, 0);
    k_pool<<<(Nr + POOL_CH - 1) / POOL_CH, 256>>>(r_acc, r_bat, r_b, r_cnt, Nr, 64, NG);

    k_final<<<1, 256>>>(linW, linb, out);
}